// round 1
// baseline (speedup 1.0000x reference)
#include <cuda_runtime.h>
#include <math.h>

#define Bc 2
#define Tc 4096
#define Ec 1024
#define Hc 16
#define Dc 64
#define Mc 8
#define Pc 64
#define PMc 512
#define CHc 128
#define NCc 32
#define BHc 32

// ---------------- scratch (device globals; no allocations allowed) ----------
__device__ float g_qkv[(size_t)Bc*Tc*3*Ec];          // 100 MB
__device__ float g_qn [(size_t)BHc*Tc*Dc];           // 32 MB
__device__ float g_kn [(size_t)BHc*Tc*Dc];
__device__ float g_v  [(size_t)BHc*Tc*Dc];
__device__ float g_qf [(size_t)BHc*NCc*PMc*CHc];     // 268 MB, layout (b,h,c, f, i)
__device__ float g_kf [(size_t)BHc*NCc*PMc*CHc];
__device__ float g_ckv[(size_t)BHc*NCc*PMc*Dc];      // 268 MB, layout (b,h,c, f, d)
__device__ float g_ks [(size_t)BHc*NCc*PMc];
__device__ float g_o  [(size_t)BHc*Tc*Dc];
__device__ float g_nrm[(size_t)BHc*Tc];

// ---------------- generic fp32 GEMM: C[M,N] = A[M,K] @ W[N,K]^T + bias ------
__global__ __launch_bounds__(256) void gemm_bias_k(
    const float* __restrict__ A, const float* __restrict__ W,
    const float* __restrict__ bias, float* __restrict__ C, int N, int K)
{
    __shared__ float As[16][128];
    __shared__ float Bs[16][128];
    int tid = threadIdx.x;
    int bm = blockIdx.y * 128, bn = blockIdx.x * 128;
    int tm = (tid >> 4) << 3, tn = (tid & 15) << 3;
    float acc[8][8] = {};
    for (int k0 = 0; k0 < K; k0 += 16) {
        #pragma unroll
        for (int l = 0; l < 2; l++) {
            int idx = tid * 2 + l;
            int r = idx >> 2, c = (idx & 3) << 2;
            float4 va = *(const float4*)(A + (size_t)(bm + r) * K + k0 + c);
            As[c+0][r]=va.x; As[c+1][r]=va.y; As[c+2][r]=va.z; As[c+3][r]=va.w;
            float4 vb = *(const float4*)(W + (size_t)(bn + r) * K + k0 + c);
            Bs[c+0][r]=vb.x; Bs[c+1][r]=vb.y; Bs[c+2][r]=vb.z; Bs[c+3][r]=vb.w;
        }
        __syncthreads();
        #pragma unroll
        for (int kk = 0; kk < 16; kk++) {
            float a[8], b[8];
            *(float4*)(a)   = *(const float4*)&As[kk][tm];
            *(float4*)(a+4) = *(const float4*)&As[kk][tm+4];
            *(float4*)(b)   = *(const float4*)&Bs[kk][tn];
            *(float4*)(b+4) = *(const float4*)&Bs[kk][tn+4];
            #pragma unroll
            for (int i = 0; i < 8; i++)
                #pragma unroll
                for (int j = 0; j < 8; j++)
                    acc[i][j] += a[i] * b[j];
        }
        __syncthreads();
    }
    #pragma unroll
    for (int i = 0; i < 8; i++) {
        #pragma unroll
        for (int j = 0; j < 8; j += 4) {
            float4 o;
            o.x = acc[i][j+0] + bias[bn+tn+j+0];
            o.y = acc[i][j+1] + bias[bn+tn+j+1];
            o.z = acc[i][j+2] + bias[bn+tn+j+2];
            o.w = acc[i][j+3] + bias[bn+tn+j+3];
            *(float4*)(C + (size_t)(bm+tm+i)*N + bn+tn+j) = o;
        }
    }
}

// ---------------- output GEMM: reads A from g_o (B,H,T,D) layout ------------
__global__ __launch_bounds__(256) void gemm_out_k(
    const float* __restrict__ W, const float* __restrict__ bias, float* __restrict__ C)
{
    __shared__ float As[16][128];
    __shared__ float Bs[16][128];
    const int K = Ec, N = Ec;
    int tid = threadIdx.x;
    int bm = blockIdx.y * 128, bn = blockIdx.x * 128;
    int tm = (tid >> 4) << 3, tn = (tid & 15) << 3;
    float acc[8][8] = {};
    for (int k0 = 0; k0 < K; k0 += 16) {
        int h = k0 >> 6;
        #pragma unroll
        for (int l = 0; l < 2; l++) {
            int idx = tid * 2 + l;
            int r = idx >> 2, cc = (idx & 3) << 2;
            int rg = bm + r;
            int b = rg >> 12, t = rg & 4095;
            int d = (k0 & 63) + cc;
            float4 va = *(const float4*)(g_o + ((size_t)(b*Hc + h)*Tc + t)*Dc + d);
            As[cc+0][r]=va.x; As[cc+1][r]=va.y; As[cc+2][r]=va.z; As[cc+3][r]=va.w;
            float4 vb = *(const float4*)(W + (size_t)(bn + r)*K + k0 + cc);
            Bs[cc+0][r]=vb.x; Bs[cc+1][r]=vb.y; Bs[cc+2][r]=vb.z; Bs[cc+3][r]=vb.w;
        }
        __syncthreads();
        #pragma unroll
        for (int kk = 0; kk < 16; kk++) {
            float a[8], b[8];
            *(float4*)(a)   = *(const float4*)&As[kk][tm];
            *(float4*)(a+4) = *(const float4*)&As[kk][tm+4];
            *(float4*)(b)   = *(const float4*)&Bs[kk][tn];
            *(float4*)(b+4) = *(const float4*)&Bs[kk][tn+4];
            #pragma unroll
            for (int i = 0; i < 8; i++)
                #pragma unroll
                for (int j = 0; j < 8; j++)
                    acc[i][j] += a[i] * b[j];
        }
        __syncthreads();
    }
    #pragma unroll
    for (int i = 0; i < 8; i++) {
        #pragma unroll
        for (int j = 0; j < 8; j += 4) {
            float4 o;
            o.x = acc[i][j+0] + bias[bn+tn+j+0];
            o.y = acc[i][j+1] + bias[bn+tn+j+1];
            o.z = acc[i][j+2] + bias[bn+tn+j+2];
            o.w = acc[i][j+3] + bias[bn+tn+j+3];
            *(float4*)(C + (size_t)(bm+tm+i)*N + bn+tn+j) = o;
        }
    }
}

// ---------------- split qkv into heads, l2-normalize q,k --------------------
__global__ void split_norm_k()
{
    int gid = blockIdx.x;                 // b*T*H + t*H + h  (= (b*T+t)*16 + h)
    int h = gid & 15;
    int bt = gid >> 4;
    int lane = threadIdx.x;               // 32 threads
    const float* row = g_qkv + (size_t)bt * (3*Ec);
    int col = h*64 + lane;
    float q0 = row[col],        q1 = row[col+32];
    float k0 = row[Ec+col],     k1 = row[Ec+col+32];
    float v0 = row[2*Ec+col],   v1 = row[2*Ec+col+32];
    float sq = q0*q0 + q1*q1;
    float sk = k0*k0 + k1*k1;
    #pragma unroll
    for (int off = 16; off > 0; off >>= 1) {
        sq += __shfl_xor_sync(0xffffffffu, sq, off);
        sk += __shfl_xor_sync(0xffffffffu, sk, off);
    }
    float rq = 1.f / fmaxf(sqrtf(sq), 1e-12f);
    float rk = 1.f / fmaxf(sqrtf(sk), 1e-12f);
    int b = bt >> 12, t = bt & 4095;
    size_t o = ((size_t)(b*Hc + h)*Tc + t)*Dc + lane;
    g_qn[o] = q0*rq; g_qn[o+32] = q1*rq;
    g_kn[o] = k0*rk; g_kn[o+32] = k1*rk;
    g_v[o]  = v0;    g_v[o+32]  = v1;
}

// ---------------- feature map: (poly x prf) per chunk, token-minor layout ---
__global__ __launch_bounds__(256) void features_k(
    const float* __restrict__ omega, const float* __restrict__ poly_w,
    const float* __restrict__ qnodes, const float* __restrict__ qweights)
{
    __shared__ float xs[64*129];    // [d][i], padded
    __shared__ float om[64*8];
    __shared__ float prf[128*8];
    int bhc = blockIdx.x;
    int isK = blockIdx.y;
    int bh = bhc >> 5, c = bhc & 31;
    int h = bh & 15;
    const float* src = (isK ? g_kn : g_qn) + ((size_t)bh*Tc + c*CHc)*Dc;
    float* dst = (isK ? g_kf : g_qf) + (size_t)bhc*PMc*CHc;
    int tid = threadIdx.x;
    #pragma unroll
    for (int l = 0; l < 32; l++) {
        int idx = tid + l*256;
        int i = idx >> 6, d = idx & 63;
        xs[d*129 + i] = src[(size_t)i*64 + d];
    }
    om[tid & 511] = 0.f;  // placeholder overwritten below (keeps compiler happy)
    om[tid]       = omega[h*512 + tid];
    om[tid + 256] = omega[h*512 + tid + 256];
    __syncthreads();
    float s0 = qnodes[0];
    float sq2s = sqrtf(fmaxf(2.f*s0, 0.f));
    float wq = sqrtf(fmaxf(qweights[0], 0.f));
    float prescale = 0.3535533905932738f * wq;   // (1/sqrt(M)) * sqrt(w)
    #pragma unroll
    for (int l = 0; l < 4; l++) {
        int pair = tid + l*256;
        int i = pair >> 3, m = pair & 7;
        float a = 0.f;
        #pragma unroll
        for (int d = 0; d < 64; d++) a += xs[d*129 + i] * om[d*8 + m];
        float e = fminf(fmaxf(a * sq2s - s0, -20.f), 20.f);
        prf[i*8 + m] = expf(e) * prescale;
    }
    __syncthreads();
    int ti = (tid >> 4) << 3, tp = (tid & 15) << 2;
    float acc[8][4] = {};
    const float* pwp = poly_w + h*4096;
    for (int d = 0; d < 64; d++) {
        float a[8];
        #pragma unroll
        for (int x = 0; x < 8; x++) a[x] = xs[d*129 + ti + x];
        float4 bb = *(const float4*)(pwp + d*64 + tp);
        #pragma unroll
        for (int i2 = 0; i2 < 8; i2++) {
            acc[i2][0] += a[i2]*bb.x; acc[i2][1] += a[i2]*bb.y;
            acc[i2][2] += a[i2]*bb.z; acc[i2][3] += a[i2]*bb.w;
        }
    }
    #pragma unroll
    for (int i2 = 0; i2 < 8; i2++)
        #pragma unroll
        for (int j = 0; j < 4; j++)
            acc[i2][j] = acc[i2][j]*acc[i2][j]*0.125f;   // square / sqrt(P)
    #pragma unroll
    for (int j = 0; j < 4; j++) {
        int p = tp + j;
        #pragma unroll
        for (int m = 0; m < 8; m++) {
            float vals[8];
            #pragma unroll
            for (int i2 = 0; i2 < 8; i2++) vals[i2] = acc[i2][j] * prf[(ti+i2)*8 + m];
            float* outp = dst + (size_t)(p*8 + m)*CHc + ti;
            *(float4*)outp     = *(float4*)vals;
            *(float4*)(outp+4) = *(float4*)(vals+4);
        }
    }
}

// ---------------- pass A: per-chunk  kv[f][d] = sum_i kf[f][i] v[i][d] ------
__global__ __launch_bounds__(256) void passA_k()
{
    __shared__ float kfs[64*33];   // [f'][ii]
    __shared__ float vs[32*64];    // [ii][d]
    int bhc = blockIdx.x;
    int f0 = blockIdx.y << 6;
    int bh = bhc >> 5, c = bhc & 31;
    const float* kfbase = g_kf + (size_t)bhc*PMc*CHc + (size_t)f0*CHc;
    const float* vbase = g_v + ((size_t)bh*Tc + c*CHc)*Dc;
    int tid = threadIdx.x;
    int tf = (tid >> 4) << 2, td = (tid & 15) << 2;
    float acc[4][4] = {};
    float kssum = 0.f;
    for (int i0 = 0; i0 < 128; i0 += 32) {
        #pragma unroll
        for (int l = 0; l < 8; l++) {
            int idx = tid + l*256;
            int f = idx >> 5, ii = idx & 31;
            kfs[f*33 + ii] = kfbase[(size_t)f*CHc + i0 + ii];
        }
        #pragma unroll
        for (int l = 0; l < 2; l++) {
            int idx = tid + l*256;
            int ii = idx >> 4, d = (idx & 15) << 2;
            *(float4*)&vs[ii*64 + d] = *(const float4*)(vbase + (size_t)(i0+ii)*64 + d);
        }
        __syncthreads();
        if (tid < 64) {
            float s = 0.f;
            #pragma unroll
            for (int ii = 0; ii < 32; ii++) s += kfs[tid*33 + ii];
            kssum += s;
        }
        #pragma unroll
        for (int kk = 0; kk < 32; kk++) {
            float a[4];
            #pragma unroll
            for (int x = 0; x < 4; x++) a[x] = kfs[(tf+x)*33 + kk];
            float4 bv = *(const float4*)&vs[kk*64 + td];
            #pragma unroll
            for (int i = 0; i < 4; i++) {
                acc[i][0]+=a[i]*bv.x; acc[i][1]+=a[i]*bv.y;
                acc[i][2]+=a[i]*bv.z; acc[i][3]+=a[i]*bv.w;
            }
        }
        __syncthreads();
    }
    float* outp = g_ckv + (size_t)bhc*PMc*Dc + (size_t)f0*Dc;
    #pragma unroll
    for (int i = 0; i < 4; i++) {
        float4 o = make_float4(acc[i][0],acc[i][1],acc[i][2],acc[i][3]);
        *(float4*)(outp + (size_t)(tf+i)*64 + td) = o;
    }
    if (tid < 64) g_ks[(size_t)bhc*PMc + f0 + tid] = kssum;
}

// ---------------- exclusive prefix over chunks (state assembly) -------------
__global__ void prefix_kv_k()
{
    size_t idx = (size_t)blockIdx.x*256 + threadIdx.x;   // < BH*PM*D
    size_t bh = idx / (PMc*Dc);
    size_t rem = idx % (PMc*Dc);
    float acc = 0.f;
    #pragma unroll
    for (int c = 0; c < NCc; c++) {
        size_t p = (bh*NCc + c)*(size_t)(PMc*Dc) + rem;
        float v = g_ckv[p];
        g_ckv[p] = acc;
        acc += v;
    }
}
__global__ void prefix_ks_k()
{
    size_t idx = (size_t)blockIdx.x*256 + threadIdx.x;   // < BH*PM
    size_t bh = idx / PMc;
    size_t rem = idx % PMc;
    float acc = 0.f;
    #pragma unroll
    for (int c = 0; c < NCc; c++) {
        size_t p = (bh*NCc + c)*(size_t)PMc + rem;
        float v = g_ks[p];
        g_ks[p] = acc;
        acc += v;
    }
}

// ---------------- pass C1: masked scores, intra context, row sums -----------
__global__ __launch_bounds__(256) void chunk_scores_k()
{
    extern __shared__ float sm[];
    float* S = sm;                       // [128][129]
    float* tiles = sm + 128*129;         // 8192 floats: phase1 qf/kf tiles OR phase2 v
    float* qs  = tiles;                  // [16][128]
    float* ks2 = tiles + 16*128;         // [16][128]
    int bhc = blockIdx.x;
    int bh = bhc >> 5, c = bhc & 31;
    const float* qb = g_qf + (size_t)bhc*PMc*CHc;
    const float* kb = g_kf + (size_t)bhc*PMc*CHc;
    int tid = threadIdx.x;
    int tm = (tid >> 4) << 3, tn = (tid & 15) << 3;
    float acc[8][8] = {};
    for (int k0 = 0; k0 < PMc; k0 += 16) {
        #pragma unroll
        for (int l = 0; l < 2; l++) {
            int idx = tid*2 + l;
            int r = idx >> 5, cc = (idx & 31) << 2;
            *(float4*)&qs[r*128 + cc]  = *(const float4*)(qb + (size_t)(k0+r)*CHc + cc);
            *(float4*)&ks2[r*128 + cc] = *(const float4*)(kb + (size_t)(k0+r)*CHc + cc);
        }
        __syncthreads();
        #pragma unroll
        for (int kk = 0; kk < 16; kk++) {
            float a[8], b[8];
            *(float4*)(a)   = *(const float4*)&qs[kk*128 + tm];
            *(float4*)(a+4) = *(const float4*)&qs[kk*128 + tm + 4];
            *(float4*)(b)   = *(const float4*)&ks2[kk*128 + tn];
            *(float4*)(b+4) = *(const float4*)&ks2[kk*128 + tn + 4];
            #pragma unroll
            for (int i = 0; i < 8; i++)
                #pragma unroll
                for (int j = 0; j < 8; j++)
                    acc[i][j] += a[i]*b[j];
        }
        __syncthreads();
    }
    // mask, stash S, row sums
    #pragma unroll
    for (int i = 0; i < 8; i++) {
        int ri = tm + i;
        float s = 0.f;
        #pragma unroll
        for (int j = 0; j < 8; j++) {
            int cj = tn + j;
            float v = (cj <= ri) ? acc[i][j] : 0.f;
            S[ri*129 + cj] = v;
            s += v;
        }
        #pragma unroll
        for (int off = 8; off > 0; off >>= 1) s += __shfl_xor_sync(0xffffffffu, s, off);
        if ((tid & 15) == 0) g_nrm[(size_t)bh*Tc + c*CHc + ri] = s;
    }
    __syncthreads();
    // phase 2: intra = S @ v
    float* vsm = tiles;                  // [128][64]
    #pragma unroll
    for (int l = 0; l < 8; l++) {
        int idx = tid + l*256;
        int ii = idx >> 4, d = (idx & 15) << 2;
        *(float4*)&vsm[ii*64 + d] =
            *(const float4*)(g_v + ((size_t)bh*Tc + c*CHc + ii)*Dc + d);
    }
    __syncthreads();
    int ti = tm;
    int td = (tid & 15) << 2;
    float o[8][4] = {};
    for (int k = 0; k < 128; k++) {
        float4 bv = *(const float4*)&vsm[k*64 + td];
        #pragma unroll
        for (int i = 0; i < 8; i++) {
            float a = S[(ti+i)*129 + k];
            o[i][0]+=a*bv.x; o[i][1]+=a*bv.y; o[i][2]+=a*bv.z; o[i][3]+=a*bv.w;
        }
    }
    #pragma unroll
    for (int i = 0; i < 8; i++) {
        float4 ov = make_float4(o[i][0],o[i][1],o[i][2],o[i][3]);
        *(float4*)(g_o + ((size_t)bh*Tc + c*CHc + ti + i)*Dc + td) = ov;
    }
}

// ---------------- pass C2: history context + norm + finalize ----------------
__global__ __launch_bounds__(256) void chunk_hist_k()
{
    __shared__ float qs[16*128];
    __shared__ float kvs[16*64];
    __shared__ float kst[16];
    int bhc = blockIdx.x;
    int bh = bhc >> 5, c = bhc & 31;
    const float* qb  = g_qf  + (size_t)bhc*PMc*CHc;
    const float* kvb = g_ckv + (size_t)bhc*PMc*Dc;
    const float* ksb = g_ks  + (size_t)bhc*PMc;
    int tid = threadIdx.x;
    int ti = (tid >> 4) << 3, td = (tid & 15) << 2;
    float acc[8][4] = {};
    float an[8] = {};
    for (int k0 = 0; k0 < PMc; k0 += 16) {
        #pragma unroll
        for (int l = 0; l < 2; l++) {
            int idx = tid*2 + l;
            int r = idx >> 5, cc = (idx & 31) << 2;
            *(float4*)&qs[r*128 + cc] = *(const float4*)(qb + (size_t)(k0+r)*CHc + cc);
        }
        {
            int r = tid >> 4, cc = (tid & 15) << 2;
            *(float4*)&kvs[r*64 + cc] = *(const float4*)(kvb + (size_t)(k0+r)*Dc + cc);
        }
        if (tid < 16) kst[tid] = ksb[k0 + tid];
        __syncthreads();
        #pragma unroll
        for (int kk = 0; kk < 16; kk++) {
            float a[8];
            *(float4*)(a)   = *(const float4*)&qs[kk*128 + ti];
            *(float4*)(a+4) = *(const float4*)&qs[kk*128 + ti + 4];
            float4 bv = *(const float4*)&kvs[kk*64 + td];
            float ksv = kst[kk];
            #pragma unroll
            for (int i = 0; i < 8; i++) {
                an[i] += a[i]*ksv;
                acc[i][0]+=a[i]*bv.x; acc[i][1]+=a[i]*bv.y;
                acc[i][2]+=a[i]*bv.z; acc[i][3]+=a[i]*bv.w;
            }
        }
        __syncthreads();
    }
    #pragma unroll
    for (int i = 0; i < 8; i++) {
        size_t tok = (size_t)bh*Tc + c*CHc + ti + i;
        float nrm = an[i] + g_nrm[tok] + 1e-6f;
        float inv = 1.f / nrm;
        float4* po = (float4*)(g_o + tok*Dc + td);
        float4 cur = *po;
        cur.x = (cur.x + acc[i][0]) * inv;
        cur.y = (cur.y + acc[i][1]) * inv;
        cur.z = (cur.z + acc[i][2]) * inv;
        cur.w = (cur.w + acc[i][3]) * inv;
        *po = cur;
    }
}

// ---------------- host launcher ---------------------------------------------
extern "C" void kernel_launch(void* const* d_in, const int* in_sizes, int n_in,
                              void* d_out, int out_size)
{
    const float* x        = (const float*)d_in[0];
    const float* qkv_w    = (const float*)d_in[1];
    const float* qkv_b    = (const float*)d_in[2];
    const float* out_w    = (const float*)d_in[3];
    const float* out_b    = (const float*)d_in[4];
    const float* omega    = (const float*)d_in[5];
    const float* poly_w   = (const float*)d_in[6];
    const float* qnodes   = (const float*)d_in[7];
    const float* qweights = (const float*)d_in[8];
    float* out = (float*)d_out;

    float* qkv_ptr = 0;
    cudaGetSymbolAddress((void**)&qkv_ptr, g_qkv);

    // 1) QKV GEMM: (8192 x 3072) = x @ qkv_w^T + b
    gemm_bias_k<<<dim3(3*Ec/128, (Bc*Tc)/128), 256>>>(x, qkv_w, qkv_b, qkv_ptr, 3*Ec, Ec);
    // 2) head split + l2norm
    split_norm_k<<<Bc*Tc*Hc, 32>>>();
    // 3) feature maps for q and k
    features_k<<<dim3(BHc*NCc, 2), 256>>>(omega, poly_w, qnodes, qweights);
    // 4) per-chunk kv contributions + per-chunk k sums
    passA_k<<<dim3(BHc*NCc, PMc/64), 256>>>();
    // 5) exclusive prefix over chunks
    prefix_kv_k<<<(BHc*PMc*Dc)/256, 256>>>();
    prefix_ks_k<<<(BHc*PMc)/256, 256>>>();
    // 6) intra-chunk masked scores + intra context + row sums
    cudaFuncSetAttribute(chunk_scores_k, cudaFuncAttributeMaxDynamicSharedMemorySize, 98816);
    chunk_scores_k<<<BHc*NCc, 256, 98816>>>();
    // 7) history context + normalization
    chunk_hist_k<<<BHc*NCc, 256>>>();
    // 8) output projection
    gemm_out_k<<<dim3(Ec/128, (Bc*Tc)/128), 256>>>(out_w, out_b, out);
}